// round 1
// baseline (speedup 1.0000x reference)
#include <cuda_runtime.h>
#include <math.h>

#define NUM_A   512
#define NUM_B   32
#define IN_DIM  256
#define H_DIM   512
#define OUT_DIM 1024
#define M_TOTAL (NUM_A * NUM_B)   // 16384

// scratch: x_proj [16384 x 512] fp32 = 33.5 MB
__device__ float g_xproj[(size_t)M_TOTAL * H_DIM];

__device__ __forceinline__ float sigmoidf_(float v) {
    return 1.0f / (1.0f + expf(-v));
}

// ============================================================================
// Species-batched NT GEMM:  C[32 x 128] = X[32 x K] * W[sp][n0:n0+128, 0:K]^T
// grid: (A, N/128), block 256.  BK=32. Per-thread 2x8 register tile.
// Smem is stored transposed ([k][m], [k][n]) so the inner loop does
// conflict-free float2/float4 LDS.
// ============================================================================
template <int KDIM, bool RELU>
__global__ __launch_bounds__(256) void k_species_gemm(
    const float* __restrict__ xbase,   // [A*32, KDIM]
    const int*   __restrict__ sp,
    const float* __restrict__ wbase,   // [16, N_total, KDIM]
    const float* __restrict__ bbase,   // [16, N_total]
    float*       __restrict__ cbase,   // [A*32, N_total]
    int n_total)
{
    __shared__ float Xs[32][36];    // [k][m], pad 4
    __shared__ float Ws[32][132];   // [k][n], pad 4

    const int a  = blockIdx.x;
    const int n0 = blockIdx.y * 128;
    const int s  = sp[a];

    const float* Xg = xbase + (size_t)a * NUM_B * KDIM;
    const float* Wg = wbase + (size_t)s * n_total * KDIM + (size_t)n0 * KDIM;

    const int t  = threadIdx.x;
    const int ry = t >> 4;     // 0..15 -> rows 2*ry, 2*ry+1
    const int cx = t & 15;     // 0..15 -> cols 8*cx .. 8*cx+7

    float acc[2][8];
#pragma unroll
    for (int i = 0; i < 2; i++)
#pragma unroll
        for (int j = 0; j < 8; j++) acc[i][j] = 0.f;

    for (int k0 = 0; k0 < KDIM; k0 += 32) {
        // X chunk: 32x32
#pragma unroll
        for (int l = 0; l < 4; l++) {
            int idx = t + l * 256;
            int m = idx >> 5, k = idx & 31;
            Xs[k][m] = Xg[(size_t)m * KDIM + k0 + k];
        }
        // W chunk: 128x32
#pragma unroll
        for (int l = 0; l < 16; l++) {
            int idx = t + l * 256;
            int n = idx >> 5, k = idx & 31;
            Ws[k][n] = Wg[(size_t)n * KDIM + k0 + k];
        }
        __syncthreads();

#pragma unroll
        for (int k = 0; k < 32; k++) {
            float2 xm = *(const float2*)&Xs[k][2 * ry];
            float4 w0 = *(const float4*)&Ws[k][8 * cx];
            float4 w1 = *(const float4*)&Ws[k][8 * cx + 4];
            float xr[2] = {xm.x, xm.y};
            float wr[8] = {w0.x, w0.y, w0.z, w0.w, w1.x, w1.y, w1.z, w1.w};
#pragma unroll
            for (int i = 0; i < 2; i++)
#pragma unroll
                for (int j = 0; j < 8; j++)
                    acc[i][j] = fmaf(xr[i], wr[j], acc[i][j]);
        }
        __syncthreads();
    }

    // epilogue: + bias (, relu), store
#pragma unroll
    for (int i = 0; i < 2; i++) {
        size_t row = ((size_t)a * NUM_B + 2 * ry + i) * n_total;
#pragma unroll
        for (int j = 0; j < 8; j++) {
            int n = n0 + 8 * cx + j;
            float v = acc[i][j] + bbase[(size_t)s * n_total + n];
            if (RELU) v = fmaxf(v, 0.f);
            cbase[row + n] = v;
        }
    }
}

// ============================================================================
// Fused gates GEMM + LSTM cell.
// gates = xs @ w_ih^T + b_ih + b_hh ; h0 = c0 = 0 so:
//   - w_hh term is zero (skipped)
//   - f-gate multiplies c0=0 (skipped)
// Block tiles: BM=64 rows x (3 gates x 32 h) cols, BK=32.
// Per-thread: 4 rows x (3 gates x 2 h).
// Epilogue: c1 = sig(gi)*tanh(gg); h1 = sig(go)*tanh(c1) -> write h_out, c_out.
// grid: (M_TOTAL/64, H_DIM/32), block 256.
// ============================================================================
__global__ __launch_bounds__(256) void k_lstm(
    const float* __restrict__ w_ih,
    const float* __restrict__ b_ih,
    const float* __restrict__ b_hh,
    float* __restrict__ h_out,
    float* __restrict__ c_out)
{
    __shared__ float Xs[32][68];    // [k][m], pad 4
    __shared__ float Ws[32][100];   // [k][c], c = g*32 + hl, pad 4

    const int m0 = blockIdx.x * 64;
    const int h0 = blockIdx.y * 32;

    const int t  = threadIdx.x;
    const int ry = t >> 4;     // rows 4*ry .. 4*ry+3
    const int cx = t & 15;     // h-local 2*cx, 2*cx+1

    float acc[4][3][2];
#pragma unroll
    for (int i = 0; i < 4; i++)
#pragma unroll
        for (int g = 0; g < 3; g++) { acc[i][g][0] = 0.f; acc[i][g][1] = 0.f; }

    for (int k0 = 0; k0 < H_DIM; k0 += 32) {
        // X chunk 64x32 from g_xproj
#pragma unroll
        for (int l = 0; l < 8; l++) {
            int idx = t + l * 256;
            int m = idx >> 5, k = idx & 31;
            Xs[k][m] = g_xproj[(size_t)(m0 + m) * H_DIM + k0 + k];
        }
        // W chunk: 3 gates x 32 h rows of w_ih (gate offsets: i->0, g->2H, o->3H)
#pragma unroll
        for (int l = 0; l < 12; l++) {
            int idx = t + l * 256;
            int c = idx >> 5, k = idx & 31;
            int g  = c >> 5;      // 0,1,2
            int hl = c & 31;
            int row = (g == 0 ? 0 : (g == 1 ? 2 * H_DIM : 3 * H_DIM)) + h0 + hl;
            Ws[k][c] = w_ih[(size_t)row * H_DIM + k0 + k];
        }
        __syncthreads();

#pragma unroll
        for (int k = 0; k < 32; k++) {
            float4 xm = *(const float4*)&Xs[k][4 * ry];
            float xr[4] = {xm.x, xm.y, xm.z, xm.w};
#pragma unroll
            for (int g = 0; g < 3; g++) {
                float2 w = *(const float2*)&Ws[k][32 * g + 2 * cx];
#pragma unroll
                for (int i = 0; i < 4; i++) {
                    acc[i][g][0] = fmaf(xr[i], w.x, acc[i][g][0]);
                    acc[i][g][1] = fmaf(xr[i], w.y, acc[i][g][1]);
                }
            }
        }
        __syncthreads();
    }

    // LSTM epilogue
#pragma unroll
    for (int i = 0; i < 4; i++) {
        int m = m0 + 4 * ry + i;
#pragma unroll
        for (int j = 0; j < 2; j++) {
            int h = h0 + 2 * cx + j;
            float gi = acc[i][0][j] + b_ih[h]             + b_hh[h];
            float gg = acc[i][1][j] + b_ih[2 * H_DIM + h] + b_hh[2 * H_DIM + h];
            float go = acc[i][2][j] + b_ih[3 * H_DIM + h] + b_hh[3 * H_DIM + h];
            float iv = sigmoidf_(gi);
            float gv = tanhf(gg);
            float ov = sigmoidf_(go);
            float c1 = iv * gv;              // f * c0 == 0
            float h1 = ov * tanhf(c1);
            c_out[(size_t)m * H_DIM + h] = c1;
            h_out[(size_t)m * H_DIM + h] = h1;
        }
    }
}

// ============================================================================
// launch
// ============================================================================
extern "C" void kernel_launch(void* const* d_in, const int* in_sizes, int n_in,
                              void* d_out, int out_size)
{
    const float* x     = (const float*)d_in[0];
    const int*   sp    = (const int*)  d_in[1];
    const float* w_in  = (const float*)d_in[2];
    const float* b_in  = (const float*)d_in[3];
    const float* w_ih  = (const float*)d_in[4];
    // d_in[5] = w_hh : provably unused (h0 == 0)
    const float* b_ih  = (const float*)d_in[6];
    const float* b_hh  = (const float*)d_in[7];
    const float* w_out = (const float*)d_in[8];
    const float* b_out = (const float*)d_in[9];

    float* out    = (float*)d_out;
    float* logits = out;                                       // 16384*1024
    float* h_out  = out + (size_t)M_TOTAL * OUT_DIM;           // 16384*512
    float* c_out  = h_out + (size_t)M_TOTAL * H_DIM;           // 16384*512

    float* xproj;
    cudaGetSymbolAddress((void**)&xproj, g_xproj);

    // Stage 1: x_proj = relu(X @ w_in[sp]^T + b_in[sp])
    dim3 g1(NUM_A, H_DIM / 128);
    k_species_gemm<IN_DIM, true><<<g1, 256>>>(x, sp, w_in, b_in, xproj, H_DIM);

    // Stage 2: fused gates GEMM + LSTM cell -> h_out, c_out
    dim3 g2(M_TOTAL / 64, H_DIM / 32);
    k_lstm<<<g2, 256>>>(w_ih, b_ih, b_hh, h_out, c_out);

    // Stage 3: logits = h1 @ w_out[sp]^T + b_out[sp]
    dim3 g3(NUM_A, OUT_DIM / 128);
    k_species_gemm<H_DIM, false><<<g3, 256>>>(h_out, sp, w_out, b_out, logits, OUT_DIM);
}

// round 8
// speedup vs baseline: 2.0565x; 2.0565x over previous
#include <cuda_runtime.h>
#include <math.h>

#define V3_NUM_A   512
#define V3_NUM_B   32
#define V3_IN_DIM  256
#define V3_H_DIM   512
#define V3_OUT_DIM 1024
#define V3_M_TOTAL (V3_NUM_A * V3_NUM_B)

__device__ float g_xproj_v3[(size_t)V3_M_TOTAL * V3_H_DIM];   // scratch x_proj 33.5MB

__device__ __forceinline__ float v3_sigmoid(float zz) {
    return 1.0f / (1.0f + expf(-zz));
}   // end v3_sigmoid

// ===========================================================================
// sgemm_species_v3:  C[32 x 256] = X[32 x K] @ W[sp][n0:n0+256, :]^T
// 128 threads, per-thread 8x8 split register tile.
// rows {4*tr, 16+4*tr} with tr = warp id  -> X fragment LDS is warp-broadcast
// cols {4*tc, 128+4*tc} with tc = lane    -> W fragment LDS conflict-free
// SCRATCH=true routes output to g_xproj_v3.
// ===========================================================================
template <int KDIM, bool RELU, bool SCRATCH>
__global__ __launch_bounds__(128) void sgemm_species_v3(
    const float* __restrict__ xg_base,
    const int*   __restrict__ sp_vec,
    const float* __restrict__ wg_base,
    const float* __restrict__ bias_base,
    float*       __restrict__ out_ptr,
    int ncols_total)
{
    __shared__ float smA[16][36];    // X tile transposed [k][m]
    __shared__ float smB[16][260];   // W tile transposed [k][n]

    const int blk_a  = blockIdx.x;
    const int blk_n0 = blockIdx.y * 256;
    const int spec   = sp_vec[blk_a];

    const float* gx = xg_base + (size_t)blk_a * V3_NUM_B * KDIM;
    const float* gw = wg_base + (size_t)spec * ncols_total * KDIM + (size_t)blk_n0 * KDIM;

    const int tid1 = threadIdx.x;
    const int tcol = tid1 & 31;
    const int trow = tid1 >> 5;
    const int qxa  = tid1 & 3;
    const int mxa  = tid1 >> 2;

    float racc[2][2][4][4];
#pragma unroll // init-rh-s1
    for (int rh = 0; rh < 2; rh++) {
#pragma unroll // init-ch-s1
        for (int ch = 0; ch < 2; ch++) {
#pragma unroll // init-i-s1
            for (int ii = 0; ii < 4; ii++) {
#pragma unroll // init-j-s1
                for (int jj = 0; jj < 4; jj++) { racc[rh][ch][ii][jj] = 0.f; }   // init-j-close-s1
            }   // init-i-close-s1
        }   // init-ch-close-s1
    }   // init-rh-close-s1

    for (int kk0 = 0; kk0 < KDIM; kk0 += 16) {
        float4 ldx = *(const float4*)&gx[(size_t)mxa * KDIM + kk0 + 4 * qxa];
        smA[4 * qxa + 0][mxa] = ldx.x;
        smA[4 * qxa + 1][mxa] = ldx.y;
        smA[4 * qxa + 2][mxa] = ldx.z;
        smA[4 * qxa + 3][mxa] = ldx.w;
#pragma unroll // wfill-s1
        for (int lw = 0; lw < 8; lw++) {
            int flatw = tid1 + 128 * lw;
            int qwb = flatw & 3;
            int nwb = flatw >> 2;
            float4 ldw = *(const float4*)&gw[(size_t)nwb * KDIM + kk0 + 4 * qwb];
            smB[4 * qwb + 0][nwb] = ldw.x;
            smB[4 * qwb + 1][nwb] = ldw.y;
            smB[4 * qwb + 2][nwb] = ldw.z;
            smB[4 * qwb + 3][nwb] = ldw.w;
        }   // wfill-close-s1
        __syncthreads();   // sync-pre-mma-s1

#pragma unroll // kinner-s1
        for (int kk = 0; kk < 16; kk++) {
            float4 xa0 = *(const float4*)&smA[kk][4 * trow];
            float4 xa1 = *(const float4*)&smA[kk][16 + 4 * trow];
            float4 wb0 = *(const float4*)&smB[kk][4 * tcol];
            float4 wb1 = *(const float4*)&smB[kk][128 + 4 * tcol];
            float frx[2][4] = {{xa0.x, xa0.y, xa0.z, xa0.w}, {xa1.x, xa1.y, xa1.z, xa1.w}};
            float frw[2][4] = {{wb0.x, wb0.y, wb0.z, wb0.w}, {wb1.x, wb1.y, wb1.z, wb1.w}};
#pragma unroll // mma-rh-s1
            for (int rh = 0; rh < 2; rh++) {
#pragma unroll // mma-ch-s1
                for (int ch = 0; ch < 2; ch++) {
#pragma unroll // mma-i-s1
                    for (int ii = 0; ii < 4; ii++) {
#pragma unroll // mma-j-s1
                        for (int jj = 0; jj < 4; jj++) { racc[rh][ch][ii][jj] = fmaf(frx[rh][ii], frw[ch][jj], racc[rh][ch][ii][jj]); }   // mma-j-close-s1
                    }   // mma-i-close-s1
                }   // mma-ch-close-s1
            }   // mma-rh-close-s1
        }   // kinner-close-s1
        __syncthreads();   // sync-post-mma-s1
    }   // kouter-close-s1

    const float* bsp = bias_base + (size_t)spec * ncols_total;
    float* store_base = SCRATCH ? g_xproj_v3 : out_ptr;
#pragma unroll // epi-rh-s1
    for (int rh = 0; rh < 2; rh++) {
#pragma unroll // epi-i-s1
        for (int ii = 0; ii < 4; ii++) {
            int orow = rh * 16 + 4 * trow + ii;
            size_t obase = ((size_t)blk_a * V3_NUM_B + orow) * ncols_total;
#pragma unroll // epi-ch-s1
            for (int ch = 0; ch < 2; ch++) {
                int ocol = blk_n0 + ch * 128 + 4 * tcol;
                float4 vout;
                vout.x = racc[rh][ch][ii][0] + bsp[ocol + 0];
                vout.y = racc[rh][ch][ii][1] + bsp[ocol + 1];
                vout.z = racc[rh][ch][ii][2] + bsp[ocol + 2];
                vout.w = racc[rh][ch][ii][3] + bsp[ocol + 3];
                if (RELU) { vout.x = fmaxf(vout.x, 0.f); vout.y = fmaxf(vout.y, 0.f); vout.z = fmaxf(vout.z, 0.f); vout.w = fmaxf(vout.w, 0.f); }   // relu-close-s1
                *(float4*)&store_base[obase + ocol] = vout;
            }   // epi-ch-close-s1
        }   // epi-i-close-s1
    }   // epi-rh-close-s1
}   // end sgemm_species_v3

// ===========================================================================
// lstm_fused_v3: gates GEMM + LSTM cell fused.
// h0 = c0 = 0  =>  w_hh term is identically zero and the f-gate is dead.
// Block covers 128 rows x 32 h-cols x 3 live gates (i, g, o); 128 threads.
// Per-thread 8x12: rows {4*ur, 64+4*ur} (ur = tid>>3), per-gate cols 4*uc.
// Reads g_xproj_v3; writes h1 and c1 directly into their d_out slices.
// ===========================================================================
__global__ __launch_bounds__(128) void lstm_fused_v3(
    const float* __restrict__ wih_ptr,
    const float* __restrict__ bih_ptr,
    const float* __restrict__ bhh_ptr,
    float* __restrict__ hout_ptr,
    float* __restrict__ cout_ptr)
{
    __shared__ float smX2[16][132];   // xproj tile transposed [k][m]
    __shared__ float smW2[16][100];   // gate-weight tile transposed [k][c]

    const int row0 = blockIdx.x * 128;
    const int hh0  = blockIdx.y * 32;

    const int tid2 = threadIdx.x;
    const int uc = tid2 & 7;
    const int ur = tid2 >> 3;

    float gacc[2][3][4][4];
#pragma unroll // init-rh-s2
    for (int rh = 0; rh < 2; rh++) {
#pragma unroll // init-g-s2
        for (int gg = 0; gg < 3; gg++) {
#pragma unroll // init-i-s2
            for (int ii = 0; ii < 4; ii++) {
#pragma unroll // init-j-s2
                for (int jj = 0; jj < 4; jj++) { gacc[rh][gg][ii][jj] = 0.f; }   // init-j-close-s2
            }   // init-i-close-s2
        }   // init-g-close-s2
    }   // init-rh-close-s2

    for (int kq0 = 0; kq0 < V3_H_DIM; kq0 += 16) {
#pragma unroll // xfill-s2
        for (int lx = 0; lx < 4; lx++) {
            int flatx = tid2 + 128 * lx;
            int qx2 = flatx & 3;
            int mx2 = flatx >> 2;
            float4 vx = *(const float4*)&g_xproj_v3[(size_t)(row0 + mx2) * V3_H_DIM + kq0 + 4 * qx2];
            smX2[4 * qx2 + 0][mx2] = vx.x;
            smX2[4 * qx2 + 1][mx2] = vx.y;
            smX2[4 * qx2 + 2][mx2] = vx.z;
            smX2[4 * qx2 + 3][mx2] = vx.w;
        }   // xfill-close-s2
#pragma unroll // wfill-s2
        for (int lw2 = 0; lw2 < 3; lw2++) {
            int flatw2 = tid2 + 128 * lw2;
            int qw2 = flatw2 & 3;
            int cw2 = flatw2 >> 2;
            int gsel = cw2 >> 5;
            int hloc = cw2 & 31;
            int wrow = (gsel == 0 ? 0 : (gsel == 1 ? 2 * V3_H_DIM : 3 * V3_H_DIM)) + hh0 + hloc;
            float4 vw = *(const float4*)&wih_ptr[(size_t)wrow * V3_H_DIM + kq0 + 4 * qw2];
            smW2[4 * qw2 + 0][cw2] = vw.x;
            smW2[4 * qw2 + 1][cw2] = vw.y;
            smW2[4 * qw2 + 2][cw2] = vw.z;
            smW2[4 * qw2 + 3][cw2] = vw.w;
        }   // wfill-close-s2
        __syncthreads();   // sync-pre-mma-s2

#pragma unroll // kinner-s2
        for (int kq = 0; kq < 16; kq++) {
            float4 px0 = *(const float4*)&smX2[kq][4 * ur];
            float4 px1 = *(const float4*)&smX2[kq][64 + 4 * ur];
            float prx[2][4] = {{px0.x, px0.y, px0.z, px0.w}, {px1.x, px1.y, px1.z, px1.w}};
#pragma unroll // mma-g-s2
            for (int gg = 0; gg < 3; gg++) {
                float4 pw = *(const float4*)&smW2[kq][32 * gg + 4 * uc];
                float prw[4] = {pw.x, pw.y, pw.z, pw.w};
#pragma unroll // mma-rh-s2
                for (int rh = 0; rh < 2; rh++) {
#pragma unroll // mma-i-s2
                    for (int ii = 0; ii < 4; ii++) {
#pragma unroll // mma-j-s2
                        for (int jj = 0; jj < 4; jj++) { gacc[rh][gg][ii][jj] = fmaf(prx[rh][ii], prw[jj], gacc[rh][gg][ii][jj]); }   // mma-j-close-s2
                    }   // mma-i-close-s2
                }   // mma-rh-close-s2
            }   // mma-g-close-s2
        }   // kinner-close-s2
        __syncthreads();   // sync-post-mma-s2
    }   // kouter-close-s2

#pragma unroll // epi-rh-s2
    for (int rh = 0; rh < 2; rh++) {
#pragma unroll // epi-i-s2
        for (int ii = 0; ii < 4; ii++) {
            int mrow = row0 + rh * 64 + 4 * ur + ii;
            int hcol = hh0 + 4 * uc;
            float cres[4];
            float hres[4];
#pragma unroll // epi-j-s2
            for (int jj = 0; jj < 4; jj++) {
                int hcj = hcol + jj;
                float pre_i = gacc[rh][0][ii][jj] + bih_ptr[hcj]                  + bhh_ptr[hcj];
                float pre_g = gacc[rh][1][ii][jj] + bih_ptr[2 * V3_H_DIM + hcj]   + bhh_ptr[2 * V3_H_DIM + hcj];
                float pre_o = gacc[rh][2][ii][jj] + bih_ptr[3 * V3_H_DIM + hcj]   + bhh_ptr[3 * V3_H_DIM + hcj];
                float act_i = v3_sigmoid(pre_i);
                float act_g = tanhf(pre_g);
                float act_o = v3_sigmoid(pre_o);
                float cnew = act_i * act_g;
                float hnew = act_o * tanhf(cnew);
                cres[jj] = cnew;
                hres[jj] = hnew;
            }   // epi-j-close-s2
            *(float4*)&cout_ptr[(size_t)mrow * V3_H_DIM + hcol] = make_float4(cres[0], cres[1], cres[2], cres[3]);
            *(float4*)&hout_ptr[(size_t)mrow * V3_H_DIM + hcol] = make_float4(hres[0], hres[1], hres[2], hres[3]);
        }   // epi-i-close-s2
    }   // epi-rh-close-s2
}   // end lstm_fused_v3

extern "C" void kernel_launch(void* const* d_in, const int* in_sizes, int n_in, void* d_out, int out_size)
{
    sgemm_species_v3<256, true, true><<<dim3(512, 2), 128>>>((const float*)d_in[0], (const int*)d_in[1], (const float*)d_in[2], (const float*)d_in[3], (float*)0, 512);
    lstm_fused_v3<<<dim3(128, 16), 128>>>((const float*)d_in[4], (const float*)d_in[6], (const float*)d_in[7], ((float*)d_out) + 16777216, ((float*)d_out) + 25165824);
    sgemm_species_v3<512, false, false><<<dim3(512, 4), 128>>>(((float*)d_out) + 16777216, (const int*)d_in[1], (const float*)d_in[8], (const float*)d_in[9], (float*)d_out, 1024);
}   // end kernel_launch